// round 11
// baseline (speedup 1.0000x reference)
#include <cuda_runtime.h>
#include <cuda_bf16.h>
#include <cstdint>

#define M_NODES 100000
#define E_EDGES 1600000
#define DD      128
#define NGRAPH  16

#define NC1 24
#define NC2 8
#define TILE 8192
#define STAGE 16384

#define NB_SCAN ((M_NODES + 255) / 256)   // 391
#define NTILES  ((M_NODES + 127) / 128)   // 782
#define NCHUNK  4
#define TILES_PER_CHUNK ((NTILES + NCHUNK - 1) / NCHUNK)   // 196
#define NODES_PER_CHUNK (TILES_PER_CHUNK * 128)            // 25088

// ---------------- device scratch (static: allocation-free) ----------------
__device__ __align__(16) float g_sum[(size_t)M_NODES * DD];   // edge means
__device__ __align__(16) float g_d1[(size_t)M_NODES * DD];    // partial D1 (x,u)
__device__ int   g_cnt_i[M_NODES];
__device__ int   g_off[M_NODES];
__device__ int   g_cur[M_NODES];
__device__ int   g_perm[E_EDGES];
__device__ int   g_bsum[512];
__device__ int   g_is64;
__device__ __align__(16) unsigned short Bexp1[NC1 * 128 * 32];
__device__ __align__(16) unsigned short Bexp2[NC2 * 128 * 32];

// ---------------- PTX helpers ----------------------------------------------
__device__ __forceinline__ uint32_t smem_u32(const void* p) {
    uint32_t a;
    asm("{ .reg .u64 t; cvta.to.shared.u64 t, %1; cvt.u32.u64 %0, t; }"
        : "=r"(a) : "l"(p));
    return a;
}
#define CP16(dst, src) \
    asm volatile("cp.async.ca.shared.global [%0], [%1], 16;" :: "r"(dst), "l"(src))
#define CP_COMMIT() asm volatile("cp.async.commit_group;" ::: "memory")
#define CP_WAIT1()  asm volatile("cp.async.wait_group 1;" ::: "memory")
#define CP_WAIT0()  asm volatile("cp.async.wait_group 0;" ::: "memory")
#define LDM_X4(r0, r1, r2, r3, a) \
    asm volatile("ldmatrix.sync.aligned.m8n8.x4.shared.b16 {%0,%1,%2,%3}, [%4];" \
                 : "=r"(r0), "=r"(r1), "=r"(r2), "=r"(r3) : "r"(a))
#define MMA_BF16(d, a, b0, b1) \
    asm volatile("mma.sync.aligned.m16n8k16.row.col.f32.bf16.bf16.f32 " \
                 "{%0,%1,%2,%3}, {%4,%5,%6,%7}, {%8,%9}, {%0,%1,%2,%3};" \
                 : "+f"((d)[0]), "+f"((d)[1]), "+f"((d)[2]), "+f"((d)[3]) \
                 : "r"((a)[0]), "r"((a)[1]), "r"((a)[2]), "r"((a)[3]), \
                   "r"(b0), "r"(b1))

__device__ __forceinline__ void split2(float v0, float v1,
                                       uint32_t& hp, uint32_t& lp) {
    uint32_t h2;
    asm("cvt.rn.bf16x2.f32 %0, %1, %2;" : "=r"(h2) : "f"(v1), "f"(v0));
    float h0 = __uint_as_float(h2 << 16);
    float h1 = __uint_as_float(h2 & 0xFFFF0000u);
    float l0 = v0 - h0, l1 = v1 - h1;
    asm("cvt.rn.bf16x2.f32 %0, %1, %2;" : "=r"(lp) : "f"(l1), "f"(l0));
    hp = h2;
}
__device__ __forceinline__ int edge_dest(const void* ei, int e, int is64) {
    return is64 ? (int)((const long long*)ei)[(long long)E_EDGES + e]
                : ((const int*)ei)[E_EDGES + e];
}

// ---------------- setup: dtype detect + zero counts + weight prep -----------
__global__ void setup_kernel(const unsigned int* __restrict__ ei_words,
                             const float* __restrict__ W1,
                             const float* __restrict__ W2) {
    if (blockIdx.x == 0) {
        __shared__ unsigned int s;
        if (threadIdx.x == 0) s = 0u;
        __syncthreads();
        unsigned int v = 0u;
        for (int i = threadIdx.x; i < 8192; i += blockDim.x)
            v |= ei_words[2 * i + 1];
        atomicOr(&s, v);
        __syncthreads();
        if (threadIdx.x == 0) g_is64 = (s == 0u) ? 1 : 0;
    }
    int i = blockIdx.x * blockDim.x + threadIdx.x;
    if (i < M_NODES) g_cnt_i[i] = 0;
    if (i < NC1 * 128 * 16) {
        int c = i >> 11, n = (i >> 4) & 127, k = i & 15;
        float w = W1[(c * 16 + k) * 128 + n];
        unsigned short h;
        asm("cvt.rn.bf16.f32 %0, %1;" : "=h"(h) : "f"(w));
        float l = w - __uint_as_float(((uint32_t)h) << 16);
        unsigned short lo;
        asm("cvt.rn.bf16.f32 %0, %1;" : "=h"(lo) : "f"(l));
        unsigned short* row = Bexp1 + ((size_t)c * 128 + n) * 32;
        row[k] = h; row[16 + k] = lo;
    }
    if (i < NC2 * 128 * 16) {
        int c = i >> 11, n = (i >> 4) & 127, k = i & 15;
        float w = W2[(c * 16 + k) * 128 + n];
        unsigned short h;
        asm("cvt.rn.bf16.f32 %0, %1;" : "=h"(h) : "f"(w));
        float l = w - __uint_as_float(((uint32_t)h) << 16);
        unsigned short lo;
        asm("cvt.rn.bf16.f32 %0, %1;" : "=h"(lo) : "f"(l));
        unsigned short* row = Bexp2 + ((size_t)c * 128 + n) * 32;
        row[k] = h; row[16 + k] = lo;
    }
}

// ---------------- CSR build --------------------------------------------------
__global__ void hist_kernel(const void* __restrict__ edge_index) {
    const int is64 = g_is64;
    const int stride = gridDim.x * blockDim.x;
    for (int e = blockIdx.x * blockDim.x + threadIdx.x; e < E_EDGES; e += stride)
        atomicAdd(&g_cnt_i[edge_dest(edge_index, e, is64)], 1);
}
__global__ void scan1_kernel() {
    __shared__ int s[256];
    int i = blockIdx.x * 256 + threadIdx.x;
    int v = (i < M_NODES) ? g_cnt_i[i] : 0;
    s[threadIdx.x] = v;
    __syncthreads();
    for (int d = 128; d > 0; d >>= 1) {
        if (threadIdx.x < d) s[threadIdx.x] += s[threadIdx.x + d];
        __syncthreads();
    }
    if (threadIdx.x == 0) g_bsum[blockIdx.x] = s[0];
}
__global__ void scan2_kernel() {
    __shared__ int s[512];
    int t = threadIdx.x;
    int v = (t < NB_SCAN) ? g_bsum[t] : 0;
    s[t] = v;
    __syncthreads();
    for (int d = 1; d < 512; d <<= 1) {
        int w = (t >= d) ? s[t - d] : 0;
        __syncthreads();
        s[t] += w;
        __syncthreads();
    }
    if (t < NB_SCAN) g_bsum[t] = s[t] - v;  // exclusive
}
__global__ void scan3_kernel() {
    __shared__ int s[256];
    int i = blockIdx.x * 256 + threadIdx.x;
    int v = (i < M_NODES) ? g_cnt_i[i] : 0;
    s[threadIdx.x] = v;
    __syncthreads();
    for (int d = 1; d < 256; d <<= 1) {
        int w = (threadIdx.x >= d) ? s[threadIdx.x - d] : 0;
        __syncthreads();
        s[threadIdx.x] += w;
        __syncthreads();
    }
    if (i < M_NODES) {
        int off = g_bsum[blockIdx.x] + s[threadIdx.x] - v;  // exclusive
        g_off[i] = off;
        g_cur[i] = off;
    }
}
__global__ void fill_kernel(const void* __restrict__ edge_index) {
    const int is64 = g_is64;
    const int stride = gridDim.x * blockDim.x;
    for (int e = blockIdx.x * blockDim.x + threadIdx.x; e < E_EDGES; e += stride) {
        int d = edge_dest(edge_index, e, is64);
        int pos = atomicAdd(&g_cur[d], 1);
        g_perm[pos] = e;
    }
}

// ---------------- gather (node-range chunk): warp per node, writes MEAN -----
__global__ void gather_kernel(const float* __restrict__ edge_attr,
                              int node_base, int node_count) {
    const int w    = (blockIdx.x * blockDim.x + threadIdx.x) >> 5;
    const int lane = threadIdx.x & 31;
    if (w >= node_count) return;
    const int node = node_base + w;
    const int off = g_off[node];
    const int cnt = g_cnt_i[node];
    float4 acc = make_float4(0.f, 0.f, 0.f, 0.f);
    int j = 0;
    for (; j + 8 <= cnt; j += 8) {
        float4 v[8];
        #pragma unroll
        for (int q = 0; q < 8; q++) {
            int e = g_perm[off + j + q];
            v[q] = __ldcs((const float4*)(edge_attr + (long long)e * DD + lane * 4));
        }
        #pragma unroll
        for (int q = 0; q < 8; q++) {
            acc.x += v[q].x; acc.y += v[q].y; acc.z += v[q].z; acc.w += v[q].w;
        }
    }
    for (; j < cnt; j++) {
        int e = g_perm[off + j];
        float4 v = __ldcs((const float4*)(edge_attr + (long long)e * DD + lane * 4));
        acc.x += v.x; acc.y += v.y; acc.z += v.z; acc.w += v.w;
    }
    float s = 1.0f / fmaxf((float)cnt, 1.0f);
    acc.x *= s; acc.y *= s; acc.z *= s; acc.w *= s;
    *(float4*)(g_sum + (long long)node * DD + lane * 4) = acc;
}

// ---------------- P1: D1_partial = x*W1x + u*W1u (fragments -> g_d1) ---------
#define THREADS 256
#define SMEM_P1 (2 * STAGE + 64)

__global__ __launch_bounds__(THREADS, 2)
void mlp_xu_mma(const float* __restrict__ x,
                const float* __restrict__ u,
                const void*  __restrict__ batch_ptr) {
    extern __shared__ char smem[];
    const uint32_t sbase = smem_u32(smem);
    const int tid   = threadIdx.x;
    const int wid   = tid >> 5;
    const int lane  = tid & 31;
    const int warpM = wid >> 1;
    const int warpN = wid & 1;
    const int gm0   = blockIdx.x * 128;

    const int fr = tid >> 1;
    const int hh = tid & 1;
    const int fm = gm0 + fr;
    const bool valid = fm < M_NODES;
    long long ub = 0;
    if (valid)
        ub = g_is64 ? ((const long long*)batch_ptr)[fm]
                    : (long long)((const int*)batch_ptr)[fm];
    const int fsw = (fr >> 1) & 3;
    const uint32_t a_dst_hi = (uint32_t)fr * 64 + (uint32_t)((hh ^ fsw) << 4);
    const uint32_t a_dst_lo = (uint32_t)fr * 64 + (uint32_t)(((hh + 2) ^ fsw) << 4);

    const int arow = (lane & 7) + 8 * ((lane >> 3) & 1);
    const int ac   = lane >> 4;
    const int asw  = (arow >> 1) & 3;
    const uint32_t aoff_hi = (uint32_t)arow * 64 + (uint32_t)((ac ^ asw) << 4);
    const uint32_t aoff_lo = (uint32_t)arow * 64 + (uint32_t)(((ac + 2) ^ asw) << 4);
    const int brow = (lane & 7) + 8 * (lane >> 4);
    const int bc   = (lane >> 3) & 1;
    const int bsw  = (brow >> 1) & 3;
    const uint32_t boff_hi = (uint32_t)brow * 64 + (uint32_t)((bc ^ bsw) << 4);
    const uint32_t boff_lo = (uint32_t)brow * 64 + (uint32_t)(((bc + 2) ^ bsw) << 4);

    auto load_A = [&](int c, float4& v0, float4& v1) {
        v0 = make_float4(0.f, 0.f, 0.f, 0.f); v1 = v0;
        if (valid) {
            const float* src = (c < 8)
                ? x + (long long)fm * DD + c * 16 + hh * 8
                : u + ub * DD + (c - 8) * 16 + hh * 8;
            v0 = ((const float4*)src)[0];
            v1 = ((const float4*)src)[1];
        }
    };
    auto store_A = [&](float4 v0, float4 v1, uint32_t stage) {
        uint4 hp, lp;
        split2(v0.x, v0.y, hp.x, lp.x);
        split2(v0.z, v0.w, hp.y, lp.y);
        split2(v1.x, v1.y, hp.z, lp.z);
        split2(v1.z, v1.w, hp.w, lp.w);
        *(uint4*)(smem + stage + a_dst_hi) = hp;
        *(uint4*)(smem + stage + a_dst_lo) = lp;
    };
    auto fill_B = [&](int c, uint32_t dstb) {
        const int orig = (c < 8) ? c : (c + 8);   // x chunks 0..7, u chunks 16..23
        const char* base = (const char*)(Bexp1 + (size_t)orig * 128 * 32);
        #pragma unroll
        for (int i = 0; i < 2; i++) {
            int seg = tid + i * THREADS;
            int row = seg >> 2, cc = seg & 3;
            int sw = cc ^ ((row >> 1) & 3);
            CP16(sbase + dstb + row * 64 + sw * 16, base + row * 64 + cc * 16);
        }
    };

    float acc[2][8][4];
    #pragma unroll
    for (int mt = 0; mt < 2; mt++)
        #pragma unroll
        for (int nt = 0; nt < 8; nt++)
            #pragma unroll
            for (int e = 0; e < 4; e++) acc[mt][nt][e] = 0.f;

    auto compute = [&](uint32_t Aoff, uint32_t Boff) {
        uint32_t Ah[2][4], Al[2][4];
        #pragma unroll
        for (int mt = 0; mt < 2; mt++) {
            uint32_t ab = sbase + Aoff + (uint32_t)(warpM * 32 + mt * 16) * 64;
            LDM_X4(Ah[mt][0], Ah[mt][1], Ah[mt][2], Ah[mt][3], ab + aoff_hi);
            LDM_X4(Al[mt][0], Al[mt][1], Al[mt][2], Al[mt][3], ab + aoff_lo);
        }
        uint32_t Bh[2][4], Bl[2][4];
        {
            uint32_t bb = sbase + Boff + (uint32_t)(warpN * 64) * 64;
            LDM_X4(Bh[0][0], Bh[0][1], Bh[0][2], Bh[0][3], bb + boff_hi);
            LDM_X4(Bl[0][0], Bl[0][1], Bl[0][2], Bl[0][3], bb + boff_lo);
        }
        #pragma unroll
        for (int p = 0; p < 4; p++) {
            const int cur = p & 1, nxt = cur ^ 1;
            if (p < 3) {
                uint32_t bb = sbase + Boff + (uint32_t)(warpN * 64 + (p + 1) * 16) * 64;
                LDM_X4(Bh[nxt][0], Bh[nxt][1], Bh[nxt][2], Bh[nxt][3], bb + boff_hi);
                LDM_X4(Bl[nxt][0], Bl[nxt][1], Bl[nxt][2], Bl[nxt][3], bb + boff_lo);
            }
            #pragma unroll
            for (int q = 0; q < 2; q++) {
                const int nt = p * 2 + q;
                uint32_t bh0 = Bh[cur][q * 2], bh1 = Bh[cur][q * 2 + 1];
                uint32_t bl0 = Bl[cur][q * 2], bl1 = Bl[cur][q * 2 + 1];
                #pragma unroll
                for (int mt = 0; mt < 2; mt++) {
                    MMA_BF16(acc[mt][nt], Ah[mt], bh0, bh1);
                    MMA_BF16(acc[mt][nt], Ah[mt], bl0, bl1);
                    MMA_BF16(acc[mt][nt], Al[mt], bh0, bh1);
                }
            }
        }
    };

    {
        float4 v0, v1;
        fill_B(0, 0 + TILE); CP_COMMIT();
        load_A(0, v0, v1);
        store_A(v0, v1, 0);
        CP_WAIT0();
        __syncthreads();
    }
    #pragma unroll 1
    for (int c = 0; c < 16; c++) {
        const uint32_t st  = (uint32_t)(c & 1) * STAGE;
        const uint32_t nst = (uint32_t)((c + 1) & 1) * STAGE;
        float4 v0, v1;
        const bool more = (c + 1 < 16);
        if (more) {
            fill_B(c + 1, nst + TILE); CP_COMMIT();
            load_A(c + 1, v0, v1);
        }
        compute(st, st + TILE);
        if (more) store_A(v0, v1, nst);
        CP_WAIT0();
        __syncthreads();
    }

    // store raw fragments to g_d1 (no bias/relu)
    #pragma unroll
    for (int mt = 0; mt < 2; mt++) {
        #pragma unroll
        for (int nt = 0; nt < 8; nt++) {
            int col = warpN * 64 + nt * 8 + (lane & 3) * 2;
            #pragma unroll
            for (int rr = 0; rr < 2; rr++) {
                int m = gm0 + warpM * 32 + mt * 16 + (lane >> 2) + rr * 8;
                if (m < M_NODES) {
                    *(float2*)(g_d1 + (long long)m * DD + col) =
                        make_float2(acc[mt][nt][rr * 2 + 0], acc[mt][nt][rr * 2 + 1]);
                }
            }
        }
    }
}

// ---------------- P2: agg GEMM + d1 add + relu + GEMM2 (tile chunk) ----------
#define HBASE   32768
#define CTRL    98304
#define SMEM_TOTAL (CTRL + 1024)

__global__ __launch_bounds__(THREADS, 2)
void mlp_agg_mma(const float* __restrict__ b1,
                 const float* __restrict__ b2,
                 float* __restrict__ out,
                 int tile_base) {
    extern __shared__ char smem[];
    const uint32_t sbase = smem_u32(smem);
    const int tid   = threadIdx.x;
    const int wid   = tid >> 5;
    const int lane  = tid & 31;
    const int warpM = wid >> 1;
    const int warpN = wid & 1;
    const int gm0   = (tile_base + blockIdx.x) * 128;

    float* b1s = (float*)(smem + CTRL);
    float* b2s = (float*)(smem + CTRL + 512);
    if (tid < 128) b1s[tid] = b1[tid];
    else b2s[tid - 128] = b2[tid - 128];

    const int fr = tid >> 1;
    const int hh = tid & 1;
    const int fm = gm0 + fr;
    const bool valid = fm < M_NODES;
    const int fsw = (fr >> 1) & 3;
    const uint32_t a_dst_hi = (uint32_t)fr * 64 + (uint32_t)((hh ^ fsw) << 4);
    const uint32_t a_dst_lo = (uint32_t)fr * 64 + (uint32_t)(((hh + 2) ^ fsw) << 4);

    const int arow = (lane & 7) + 8 * ((lane >> 3) & 1);
    const int ac   = lane >> 4;
    const int asw  = (arow >> 1) & 3;
    const uint32_t aoff_hi = (uint32_t)arow * 64 + (uint32_t)((ac ^ asw) << 4);
    const uint32_t aoff_lo = (uint32_t)arow * 64 + (uint32_t)(((ac + 2) ^ asw) << 4);
    const int brow = (lane & 7) + 8 * (lane >> 4);
    const int bc   = (lane >> 3) & 1;
    const int bsw  = (brow >> 1) & 3;
    const uint32_t boff_hi = (uint32_t)brow * 64 + (uint32_t)((bc ^ bsw) << 4);
    const uint32_t boff_lo = (uint32_t)brow * 64 + (uint32_t)(((bc + 2) ^ bsw) << 4);

    auto load_A = [&](int c, float4& v0, float4& v1) {
        v0 = make_float4(0.f, 0.f, 0.f, 0.f); v1 = v0;
        if (valid) {
            const float* src = g_sum + (long long)fm * DD + c * 16 + hh * 8;
            v0 = ((const float4*)src)[0];
            v1 = ((const float4*)src)[1];
        }
    };
    auto store_A = [&](float4 v0, float4 v1, uint32_t stage) {
        uint4 hp, lp;
        split2(v0.x, v0.y, hp.x, lp.x);
        split2(v0.z, v0.w, hp.y, lp.y);
        split2(v1.x, v1.y, hp.z, lp.z);
        split2(v1.z, v1.w, hp.w, lp.w);
        *(uint4*)(smem + stage + a_dst_hi) = hp;
        *(uint4*)(smem + stage + a_dst_lo) = lp;
    };
    auto fill_B = [&](const unsigned short* Bsrc, int c, uint32_t dstb) {
        const char* base = (const char*)(Bsrc + (size_t)c * 128 * 32);
        #pragma unroll
        for (int i = 0; i < 2; i++) {
            int seg = tid + i * THREADS;
            int row = seg >> 2, cc = seg & 3;
            int sw = cc ^ ((row >> 1) & 3);
            CP16(sbase + dstb + row * 64 + sw * 16, base + row * 64 + cc * 16);
        }
    };

    float acc[2][8][4];
    #pragma unroll
    for (int mt = 0; mt < 2; mt++)
        #pragma unroll
        for (int nt = 0; nt < 8; nt++)
            #pragma unroll
            for (int e = 0; e < 4; e++) acc[mt][nt][e] = 0.f;

    auto compute = [&](uint32_t Aoff, uint32_t Boff) {
        uint32_t Ah[2][4], Al[2][4];
        #pragma unroll
        for (int mt = 0; mt < 2; mt++) {
            uint32_t ab = sbase + Aoff + (uint32_t)(warpM * 32 + mt * 16) * 64;
            LDM_X4(Ah[mt][0], Ah[mt][1], Ah[mt][2], Ah[mt][3], ab + aoff_hi);
            LDM_X4(Al[mt][0], Al[mt][1], Al[mt][2], Al[mt][3], ab + aoff_lo);
        }
        uint32_t Bh[2][4], Bl[2][4];
        {
            uint32_t bb = sbase + Boff + (uint32_t)(warpN * 64) * 64;
            LDM_X4(Bh[0][0], Bh[0][1], Bh[0][2], Bh[0][3], bb + boff_hi);
            LDM_X4(Bl[0][0], Bl[0][1], Bl[0][2], Bl[0][3], bb + boff_lo);
        }
        #pragma unroll
        for (int p = 0; p < 4; p++) {
            const int cur = p & 1, nxt = cur ^ 1;
            if (p < 3) {
                uint32_t bb = sbase + Boff + (uint32_t)(warpN * 64 + (p + 1) * 16) * 64;
                LDM_X4(Bh[nxt][0], Bh[nxt][1], Bh[nxt][2], Bh[nxt][3], bb + boff_hi);
                LDM_X4(Bl[nxt][0], Bl[nxt][1], Bl[nxt][2], Bl[nxt][3], bb + boff_lo);
            }
            #pragma unroll
            for (int q = 0; q < 2; q++) {
                const int nt = p * 2 + q;
                uint32_t bh0 = Bh[cur][q * 2], bh1 = Bh[cur][q * 2 + 1];
                uint32_t bl0 = Bl[cur][q * 2], bl1 = Bl[cur][q * 2 + 1];
                #pragma unroll
                for (int mt = 0; mt < 2; mt++) {
                    MMA_BF16(acc[mt][nt], Ah[mt], bh0, bh1);
                    MMA_BF16(acc[mt][nt], Ah[mt], bl0, bl1);
                    MMA_BF16(acc[mt][nt], Al[mt], bh0, bh1);
                }
            }
        }
    };

    // ================= GEMM1 (agg chunks = Bexp1 chunks 8..15) =============
    {
        float4 v0, v1;
        fill_B(Bexp1, 8, 0 + TILE); CP_COMMIT();
        load_A(0, v0, v1);
        store_A(v0, v1, 0);
        CP_WAIT0();
        __syncthreads();
    }
    #pragma unroll 1
    for (int c = 0; c < 8; c++) {
        const uint32_t st  = (uint32_t)(c & 1) * STAGE;
        const uint32_t nst = (uint32_t)((c + 1) & 1) * STAGE;
        float4 v0, v1;
        const bool more = (c + 1 < 8);
        if (more) {
            fill_B(Bexp1, 9 + c, nst + TILE); CP_COMMIT();
            load_A(c + 1, v0, v1);
        }
        compute(st, st + TILE);
        if (more) store_A(v0, v1, nst);
        CP_WAIT0();
        __syncthreads();
    }

    // ============ add partial D1 fragments ============
    #pragma unroll
    for (int mt = 0; mt < 2; mt++) {
        #pragma unroll
        for (int nt = 0; nt < 8; nt++) {
            int col = warpN * 64 + nt * 8 + (lane & 3) * 2;
            #pragma unroll
            for (int rr = 0; rr < 2; rr++) {
                int m = gm0 + warpM * 32 + mt * 16 + (lane >> 2) + rr * 8;
                if (m < M_NODES) {
                    float2 d = *(const float2*)(g_d1 + (long long)m * DD + col);
                    acc[mt][nt][rr * 2 + 0] += d.x;
                    acc[mt][nt][rr * 2 + 1] += d.y;
                }
            }
        }
    }

    // ============ epilogue 1: H = relu(D1+b1) -> SMEM ============
    fill_B(Bexp2, 0, 0 * TILE); CP_COMMIT();
    fill_B(Bexp2, 1, 1 * TILE); CP_COMMIT();

    #pragma unroll
    for (int mt = 0; mt < 2; mt++) {
        #pragma unroll
        for (int nt = 0; nt < 8; nt++) {
            int col = warpN * 64 + nt * 8 + (lane & 3) * 2;
            float bv0 = b1s[col], bv1 = b1s[col + 1];
            int cch = col >> 4, k0 = col & 15;
            int chi = k0 >> 3, kb = (k0 & 7) * 2;
            #pragma unroll
            for (int rr = 0; rr < 2; rr++) {
                int row = warpM * 32 + mt * 16 + (lane >> 2) + rr * 8;
                float h0 = fmaxf(acc[mt][nt][rr * 2 + 0] + bv0, 0.f);
                float h1 = fmaxf(acc[mt][nt][rr * 2 + 1] + bv1, 0.f);
                uint32_t hp, lp;
                split2(h0, h1, hp, lp);
                int sw = (row >> 1) & 3;
                char* dst = smem + HBASE + cch * TILE + row * 64;
                *(uint32_t*)(dst + ((chi ^ sw) << 4) + kb)       = hp;
                *(uint32_t*)(dst + (((chi + 2) ^ sw) << 4) + kb) = lp;
                acc[mt][nt][rr * 2 + 0] = 0.f;
                acc[mt][nt][rr * 2 + 1] = 0.f;
            }
        }
    }
    CP_WAIT1();
    __syncthreads();

    // ================= GEMM2 =================
    #pragma unroll 1
    for (int c = 0; c < NC2; c++) {
        const bool more = (c + 2 < NC2);
        if (more) { fill_B(Bexp2, c + 2, (uint32_t)((c + 2) & 3) * TILE); CP_COMMIT(); }
        compute(HBASE + c * TILE, (uint32_t)(c & 3) * TILE);
        if (more) CP_WAIT1(); else CP_WAIT0();
        __syncthreads();
    }

    // ============ epilogue 2 ============
    #pragma unroll
    for (int mt = 0; mt < 2; mt++) {
        #pragma unroll
        for (int nt = 0; nt < 8; nt++) {
            int col = warpN * 64 + nt * 8 + (lane & 3) * 2;
            float bv0 = b2s[col], bv1 = b2s[col + 1];
            #pragma unroll
            for (int rr = 0; rr < 2; rr++) {
                int m = gm0 + warpM * 32 + mt * 16 + (lane >> 2) + rr * 8;
                if (m < M_NODES) {
                    float2 o = make_float2(acc[mt][nt][rr * 2 + 0] + bv0,
                                           acc[mt][nt][rr * 2 + 1] + bv1);
                    *(float2*)(out + (long long)m * DD + col) = o;
                }
            }
        }
    }
}

// ---------------- host launcher --------------------------------------------
extern "C" void kernel_launch(void* const* d_in, const int* in_sizes, int n_in,
                              void* d_out, int out_size) {
    const float* x         = (const float*)d_in[0];
    const float* edge_attr = (const float*)d_in[1];
    const float* u         = (const float*)d_in[2];
    const float* W1        = (const float*)d_in[3];
    const float* b1        = (const float*)d_in[4];
    const float* W2        = (const float*)d_in[5];
    const float* b2        = (const float*)d_in[6];
    const void*  edge_index = d_in[7];
    const void*  batch      = d_in[8];
    float* out = (float*)d_out;

    static cudaStream_t s2 = nullptr, s3 = nullptr;
    static cudaEvent_t evF = nullptr, evJ = nullptr, evE = nullptr;
    static cudaEvent_t evG[NCHUNK] = {};
    if (!s2) {
        cudaFuncSetAttribute(mlp_agg_mma,
                             cudaFuncAttributeMaxDynamicSharedMemorySize,
                             SMEM_TOTAL);
        cudaFuncSetAttribute(mlp_xu_mma,
                             cudaFuncAttributeMaxDynamicSharedMemorySize,
                             SMEM_P1);
        cudaStreamCreateWithFlags(&s2, cudaStreamNonBlocking);
        cudaStreamCreateWithFlags(&s3, cudaStreamNonBlocking);
        cudaEventCreateWithFlags(&evF, cudaEventDisableTiming);
        cudaEventCreateWithFlags(&evJ, cudaEventDisableTiming);
        cudaEventCreateWithFlags(&evE, cudaEventDisableTiming);
        for (int k = 0; k < NCHUNK; k++)
            cudaEventCreateWithFlags(&evG[k], cudaEventDisableTiming);
    }

    setup_kernel<<<NB_SCAN, 256>>>((const unsigned int*)edge_index, W1, W2);

    // fork: P1 (x,u partial GEMM) overlaps CSR build + gather
    cudaEventRecord(evF, 0);
    cudaStreamWaitEvent(s2, evF, 0);
    mlp_xu_mma<<<NTILES, THREADS, SMEM_P1, s2>>>(x, u, batch);
    cudaEventRecord(evJ, s2);

    hist_kernel<<<1184, 256>>>(edge_index);
    scan1_kernel<<<NB_SCAN, 256>>>();
    scan2_kernel<<<1, 512>>>();
    scan3_kernel<<<NB_SCAN, 256>>>();
    fill_kernel<<<1184, 256>>>(edge_index);

    // pipelined gather (stream 0) -> P2 chunks (stream s3)
    cudaStreamWaitEvent(s3, evJ, 0);
    for (int k = 0; k < NCHUNK; k++) {
        int nbase = k * NODES_PER_CHUNK;
        int ncnt  = M_NODES - nbase;
        if (ncnt > NODES_PER_CHUNK) ncnt = NODES_PER_CHUNK;
        gather_kernel<<<(ncnt * 32 + 255) / 256, 256>>>(edge_attr, nbase, ncnt);
        cudaEventRecord(evG[k], 0);
        cudaStreamWaitEvent(s3, evG[k], 0);
        int tbase = k * TILES_PER_CHUNK;
        int tcnt  = NTILES - tbase;
        if (tcnt > TILES_PER_CHUNK) tcnt = TILES_PER_CHUNK;
        mlp_agg_mma<<<tcnt, THREADS, SMEM_TOTAL, s3>>>(b1, b2, out, tbase);
    }
    cudaEventRecord(evE, s3);
    cudaStreamWaitEvent(0, evE, 0);
}

// round 12
// speedup vs baseline: 1.0133x; 1.0133x over previous
#include <cuda_runtime.h>
#include <cuda_bf16.h>
#include <cstdint>

#define M_NODES 100000
#define E_EDGES 1600000
#define DD      128
#define NGRAPH  16

#define NC1 24
#define NC2 8
#define TILE 8192
#define STAGE 16384

#define NB_SCAN ((M_NODES + 255) / 256)   // 391
#define NTILES  ((M_NODES + 127) / 128)   // 782

// ---------------- device scratch (static: allocation-free) ----------------
__device__ __align__(16) float g_sum[(size_t)M_NODES * DD];   // edge means
__device__ __align__(16) float g_d1[(size_t)M_NODES * DD];    // partial D1 (x,u)
__device__ int   g_cnt_i[M_NODES];
__device__ int   g_off[M_NODES];
__device__ int   g_cur[M_NODES];
__device__ int   g_perm[E_EDGES];
__device__ unsigned long long g_scan_desc[NB_SCAN];  // (status<<32)|value
__device__ int   g_ticket;
__device__ int   g_is64;
__device__ __align__(16) unsigned short Bexp1[NC1 * 128 * 32];
__device__ __align__(16) unsigned short Bexp2[NC2 * 128 * 32];

// ---------------- PTX helpers ----------------------------------------------
__device__ __forceinline__ uint32_t smem_u32(const void* p) {
    uint32_t a;
    asm("{ .reg .u64 t; cvta.to.shared.u64 t, %1; cvt.u32.u64 %0, t; }"
        : "=r"(a) : "l"(p));
    return a;
}
#define CP16(dst, src) \
    asm volatile("cp.async.ca.shared.global [%0], [%1], 16;" :: "r"(dst), "l"(src))
#define CP_COMMIT() asm volatile("cp.async.commit_group;" ::: "memory")
#define CP_WAIT1()  asm volatile("cp.async.wait_group 1;" ::: "memory")
#define CP_WAIT0()  asm volatile("cp.async.wait_group 0;" ::: "memory")
#define LDM_X4(r0, r1, r2, r3, a) \
    asm volatile("ldmatrix.sync.aligned.m8n8.x4.shared.b16 {%0,%1,%2,%3}, [%4];" \
                 : "=r"(r0), "=r"(r1), "=r"(r2), "=r"(r3) : "r"(a))
#define MMA_BF16(d, a, b0, b1) \
    asm volatile("mma.sync.aligned.m16n8k16.row.col.f32.bf16.bf16.f32 " \
                 "{%0,%1,%2,%3}, {%4,%5,%6,%7}, {%8,%9}, {%0,%1,%2,%3};" \
                 : "+f"((d)[0]), "+f"((d)[1]), "+f"((d)[2]), "+f"((d)[3]) \
                 : "r"((a)[0]), "r"((a)[1]), "r"((a)[2]), "r"((a)[3]), \
                   "r"(b0), "r"(b1))

__device__ __forceinline__ void split2(float v0, float v1,
                                       uint32_t& hp, uint32_t& lp) {
    uint32_t h2;
    asm("cvt.rn.bf16x2.f32 %0, %1, %2;" : "=r"(h2) : "f"(v1), "f"(v0));
    float h0 = __uint_as_float(h2 << 16);
    float h1 = __uint_as_float(h2 & 0xFFFF0000u);
    float l0 = v0 - h0, l1 = v1 - h1;
    asm("cvt.rn.bf16x2.f32 %0, %1, %2;" : "=r"(lp) : "f"(l1), "f"(l0));
    hp = h2;
}
__device__ __forceinline__ int edge_dest(const void* ei, int e, int is64) {
    return is64 ? (int)((const long long*)ei)[(long long)E_EDGES + e]
                : ((const int*)ei)[E_EDGES + e];
}

// ---------------- setup: dtype detect + zero counts + scan reset + prep -----
__global__ void setup_kernel(const unsigned int* __restrict__ ei_words,
                             const float* __restrict__ W1,
                             const float* __restrict__ W2) {
    if (blockIdx.x == 0) {
        __shared__ unsigned int s;
        if (threadIdx.x == 0) s = 0u;
        __syncthreads();
        unsigned int v = 0u;
        for (int i = threadIdx.x; i < 8192; i += blockDim.x)
            v |= ei_words[2 * i + 1];
        atomicOr(&s, v);
        __syncthreads();
        if (threadIdx.x == 0) {
            g_is64 = (s == 0u) ? 1 : 0;
            g_ticket = 0;
        }
    }
    int i = blockIdx.x * blockDim.x + threadIdx.x;
    if (i < M_NODES) g_cnt_i[i] = 0;
    if (i < NB_SCAN) g_scan_desc[i] = 0ull;
    if (i < NC1 * 128 * 16) {
        int c = i >> 11, n = (i >> 4) & 127, k = i & 15;
        float w = W1[(c * 16 + k) * 128 + n];
        unsigned short h;
        asm("cvt.rn.bf16.f32 %0, %1;" : "=h"(h) : "f"(w));
        float l = w - __uint_as_float(((uint32_t)h) << 16);
        unsigned short lo;
        asm("cvt.rn.bf16.f32 %0, %1;" : "=h"(lo) : "f"(l));
        unsigned short* row = Bexp1 + ((size_t)c * 128 + n) * 32;
        row[k] = h; row[16 + k] = lo;
    }
    if (i < NC2 * 128 * 16) {
        int c = i >> 11, n = (i >> 4) & 127, k = i & 15;
        float w = W2[(c * 16 + k) * 128 + n];
        unsigned short h;
        asm("cvt.rn.bf16.f32 %0, %1;" : "=h"(h) : "f"(w));
        float l = w - __uint_as_float(((uint32_t)h) << 16);
        unsigned short lo;
        asm("cvt.rn.bf16.f32 %0, %1;" : "=h"(lo) : "f"(l));
        unsigned short* row = Bexp2 + ((size_t)c * 128 + n) * 32;
        row[k] = h; row[16 + k] = lo;
    }
}

// ---------------- CSR build --------------------------------------------------
__global__ void hist_kernel(const void* __restrict__ edge_index) {
    const int is64 = g_is64;
    const int stride = gridDim.x * blockDim.x;
    for (int e = blockIdx.x * blockDim.x + threadIdx.x; e < E_EDGES; e += stride)
        atomicAdd(&g_cnt_i[edge_dest(edge_index, e, is64)], 1);
}

// single-pass exclusive scan (decoupled lookback, ticket-ordered blocks)
__global__ void scan_kernel() {
    __shared__ int s[256];
    __shared__ int sbid;
    __shared__ int sprefix;
    if (threadIdx.x == 0) sbid = atomicAdd(&g_ticket, 1);
    __syncthreads();
    const int bid = sbid;
    const int i = bid * 256 + threadIdx.x;
    int v = (i < M_NODES) ? g_cnt_i[i] : 0;
    s[threadIdx.x] = v;
    __syncthreads();
    #pragma unroll
    for (int d = 1; d < 256; d <<= 1) {
        int w = (threadIdx.x >= d) ? s[threadIdx.x - d] : 0;
        __syncthreads();
        s[threadIdx.x] += w;
        __syncthreads();
    }
    const int total = s[255];
    if (threadIdx.x == 0) {
        if (bid == 0) {
            atomicExch(&g_scan_desc[0],
                       (2ull << 32) | (unsigned long long)(unsigned int)total);
            sprefix = 0;
        } else {
            atomicExch(&g_scan_desc[bid],
                       (1ull << 32) | (unsigned long long)(unsigned int)total);
            int excl = 0;
            int j = bid - 1;
            while (true) {
                unsigned long long d;
                do { d = atomicAdd(&g_scan_desc[j], 0ull); } while ((d >> 32) == 0);
                excl += (int)(unsigned int)d;
                if ((d >> 32) == 2ull) break;
                j--;
            }
            atomicExch(&g_scan_desc[bid],
                       (2ull << 32) | (unsigned long long)(unsigned int)(excl + total));
            sprefix = excl;
        }
    }
    __syncthreads();
    if (i < M_NODES) {
        int off = sprefix + s[threadIdx.x] - v;   // exclusive
        g_off[i] = off;
        g_cur[i] = off;
    }
}

__global__ void fill_kernel(const void* __restrict__ edge_index) {
    const int is64 = g_is64;
    const int stride = gridDim.x * blockDim.x;
    for (int e = blockIdx.x * blockDim.x + threadIdx.x; e < E_EDGES; e += stride) {
        int d = edge_dest(edge_index, e, is64);
        int pos = atomicAdd(&g_cur[d], 1);
        g_perm[pos] = e;
    }
}

// ---------------- gather: warp per node, writes MEAN -------------------------
__global__ void gather_kernel(const float* __restrict__ edge_attr) {
    const int w    = (blockIdx.x * blockDim.x + threadIdx.x) >> 5;
    const int lane = threadIdx.x & 31;
    if (w >= M_NODES) return;
    const int off = g_off[w];
    const int cnt = g_cnt_i[w];
    float4 acc = make_float4(0.f, 0.f, 0.f, 0.f);
    int j = 0;
    for (; j + 8 <= cnt; j += 8) {
        float4 v[8];
        #pragma unroll
        for (int q = 0; q < 8; q++) {
            int e = g_perm[off + j + q];
            v[q] = __ldcs((const float4*)(edge_attr + (long long)e * DD + lane * 4));
        }
        #pragma unroll
        for (int q = 0; q < 8; q++) {
            acc.x += v[q].x; acc.y += v[q].y; acc.z += v[q].z; acc.w += v[q].w;
        }
    }
    for (; j < cnt; j++) {
        int e = g_perm[off + j];
        float4 v = __ldcs((const float4*)(edge_attr + (long long)e * DD + lane * 4));
        acc.x += v.x; acc.y += v.y; acc.z += v.z; acc.w += v.w;
    }
    float s = 1.0f / fmaxf((float)cnt, 1.0f);
    acc.x *= s; acc.y *= s; acc.z *= s; acc.w *= s;
    *(float4*)(g_sum + (long long)w * DD + lane * 4) = acc;
}

// ---------------- P1: D1_partial = x*W1x + u*W1u (fragments -> g_d1) ---------
#define THREADS 256
#define SMEM_P1 (2 * STAGE + 64)

__global__ __launch_bounds__(THREADS, 2)
void mlp_xu_mma(const float* __restrict__ x,
                const float* __restrict__ u,
                const void*  __restrict__ batch_ptr) {
    extern __shared__ char smem[];
    const uint32_t sbase = smem_u32(smem);
    const int tid   = threadIdx.x;
    const int wid   = tid >> 5;
    const int lane  = tid & 31;
    const int warpM = wid >> 1;
    const int warpN = wid & 1;
    const int gm0   = blockIdx.x * 128;

    const int fr = tid >> 1;
    const int hh = tid & 1;
    const int fm = gm0 + fr;
    const bool valid = fm < M_NODES;
    long long ub = 0;
    if (valid)
        ub = g_is64 ? ((const long long*)batch_ptr)[fm]
                    : (long long)((const int*)batch_ptr)[fm];
    const int fsw = (fr >> 1) & 3;
    const uint32_t a_dst_hi = (uint32_t)fr * 64 + (uint32_t)((hh ^ fsw) << 4);
    const uint32_t a_dst_lo = (uint32_t)fr * 64 + (uint32_t)(((hh + 2) ^ fsw) << 4);

    const int arow = (lane & 7) + 8 * ((lane >> 3) & 1);
    const int ac   = lane >> 4;
    const int asw  = (arow >> 1) & 3;
    const uint32_t aoff_hi = (uint32_t)arow * 64 + (uint32_t)((ac ^ asw) << 4);
    const uint32_t aoff_lo = (uint32_t)arow * 64 + (uint32_t)(((ac + 2) ^ asw) << 4);
    const int brow = (lane & 7) + 8 * (lane >> 4);
    const int bc   = (lane >> 3) & 1;
    const int bsw  = (brow >> 1) & 3;
    const uint32_t boff_hi = (uint32_t)brow * 64 + (uint32_t)((bc ^ bsw) << 4);
    const uint32_t boff_lo = (uint32_t)brow * 64 + (uint32_t)(((bc + 2) ^ bsw) << 4);

    auto load_A = [&](int c, float4& v0, float4& v1) {
        v0 = make_float4(0.f, 0.f, 0.f, 0.f); v1 = v0;
        if (valid) {
            const float* src = (c < 8)
                ? x + (long long)fm * DD + c * 16 + hh * 8
                : u + ub * DD + (c - 8) * 16 + hh * 8;
            v0 = ((const float4*)src)[0];
            v1 = ((const float4*)src)[1];
        }
    };
    auto store_A = [&](float4 v0, float4 v1, uint32_t stage) {
        uint4 hp, lp;
        split2(v0.x, v0.y, hp.x, lp.x);
        split2(v0.z, v0.w, hp.y, lp.y);
        split2(v1.x, v1.y, hp.z, lp.z);
        split2(v1.z, v1.w, hp.w, lp.w);
        *(uint4*)(smem + stage + a_dst_hi) = hp;
        *(uint4*)(smem + stage + a_dst_lo) = lp;
    };
    auto fill_B = [&](int c, uint32_t dstb) {
        const int orig = (c < 8) ? c : (c + 8);   // x chunks 0..7, u chunks 16..23
        const char* base = (const char*)(Bexp1 + (size_t)orig * 128 * 32);
        #pragma unroll
        for (int i = 0; i < 2; i++) {
            int seg = tid + i * THREADS;
            int row = seg >> 2, cc = seg & 3;
            int sw = cc ^ ((row >> 1) & 3);
            CP16(sbase + dstb + row * 64 + sw * 16, base + row * 64 + cc * 16);
        }
    };

    float acc[2][8][4];
    #pragma unroll
    for (int mt = 0; mt < 2; mt++)
        #pragma unroll
        for (int nt = 0; nt < 8; nt++)
            #pragma unroll
            for (int e = 0; e < 4; e++) acc[mt][nt][e] = 0.f;

    auto compute = [&](uint32_t Aoff, uint32_t Boff) {
        uint32_t Ah[2][4], Al[2][4];
        #pragma unroll
        for (int mt = 0; mt < 2; mt++) {
            uint32_t ab = sbase + Aoff + (uint32_t)(warpM * 32 + mt * 16) * 64;
            LDM_X4(Ah[mt][0], Ah[mt][1], Ah[mt][2], Ah[mt][3], ab + aoff_hi);
            LDM_X4(Al[mt][0], Al[mt][1], Al[mt][2], Al[mt][3], ab + aoff_lo);
        }
        uint32_t Bh[2][4], Bl[2][4];
        {
            uint32_t bb = sbase + Boff + (uint32_t)(warpN * 64) * 64;
            LDM_X4(Bh[0][0], Bh[0][1], Bh[0][2], Bh[0][3], bb + boff_hi);
            LDM_X4(Bl[0][0], Bl[0][1], Bl[0][2], Bl[0][3], bb + boff_lo);
        }
        #pragma unroll
        for (int p = 0; p < 4; p++) {
            const int cur = p & 1, nxt = cur ^ 1;
            if (p < 3) {
                uint32_t bb = sbase + Boff + (uint32_t)(warpN * 64 + (p + 1) * 16) * 64;
                LDM_X4(Bh[nxt][0], Bh[nxt][1], Bh[nxt][2], Bh[nxt][3], bb + boff_hi);
                LDM_X4(Bl[nxt][0], Bl[nxt][1], Bl[nxt][2], Bl[nxt][3], bb + boff_lo);
            }
            #pragma unroll
            for (int q = 0; q < 2; q++) {
                const int nt = p * 2 + q;
                uint32_t bh0 = Bh[cur][q * 2], bh1 = Bh[cur][q * 2 + 1];
                uint32_t bl0 = Bl[cur][q * 2], bl1 = Bl[cur][q * 2 + 1];
                #pragma unroll
                for (int mt = 0; mt < 2; mt++) {
                    MMA_BF16(acc[mt][nt], Ah[mt], bh0, bh1);
                    MMA_BF16(acc[mt][nt], Ah[mt], bl0, bl1);
                    MMA_BF16(acc[mt][nt], Al[mt], bh0, bh1);
                }
            }
        }
    };

    {
        float4 v0, v1;
        fill_B(0, 0 + TILE); CP_COMMIT();
        load_A(0, v0, v1);
        store_A(v0, v1, 0);
        CP_WAIT0();
        __syncthreads();
    }
    #pragma unroll 1
    for (int c = 0; c < 16; c++) {
        const uint32_t st  = (uint32_t)(c & 1) * STAGE;
        const uint32_t nst = (uint32_t)((c + 1) & 1) * STAGE;
        float4 v0, v1;
        const bool more = (c + 1 < 16);
        if (more) {
            fill_B(c + 1, nst + TILE); CP_COMMIT();
            load_A(c + 1, v0, v1);
        }
        compute(st, st + TILE);
        if (more) store_A(v0, v1, nst);
        CP_WAIT0();
        __syncthreads();
    }

    // store raw fragments to g_d1 (no bias/relu)
    #pragma unroll
    for (int mt = 0; mt < 2; mt++) {
        #pragma unroll
        for (int nt = 0; nt < 8; nt++) {
            int col = warpN * 64 + nt * 8 + (lane & 3) * 2;
            #pragma unroll
            for (int rr = 0; rr < 2; rr++) {
                int m = gm0 + warpM * 32 + mt * 16 + (lane >> 2) + rr * 8;
                if (m < M_NODES) {
                    *(float2*)(g_d1 + (long long)m * DD + col) =
                        make_float2(acc[mt][nt][rr * 2 + 0], acc[mt][nt][rr * 2 + 1]);
                }
            }
        }
    }
}

// ---------------- P2: agg GEMM + d1 add + relu + GEMM2 -----------------------
#define HBASE   32768
#define CTRL    98304
#define SMEM_TOTAL (CTRL + 1024)

__global__ __launch_bounds__(THREADS, 2)
void mlp_agg_mma(const float* __restrict__ b1,
                 const float* __restrict__ b2,
                 float* __restrict__ out) {
    extern __shared__ char smem[];
    const uint32_t sbase = smem_u32(smem);
    const int tid   = threadIdx.x;
    const int wid   = tid >> 5;
    const int lane  = tid & 31;
    const int warpM = wid >> 1;
    const int warpN = wid & 1;
    const int gm0   = blockIdx.x * 128;

    float* b1s = (float*)(smem + CTRL);
    float* b2s = (float*)(smem + CTRL + 512);
    if (tid < 128) b1s[tid] = b1[tid];
    else b2s[tid - 128] = b2[tid - 128];

    const int fr = tid >> 1;
    const int hh = tid & 1;
    const int fm = gm0 + fr;
    const bool valid = fm < M_NODES;
    const int fsw = (fr >> 1) & 3;
    const uint32_t a_dst_hi = (uint32_t)fr * 64 + (uint32_t)((hh ^ fsw) << 4);
    const uint32_t a_dst_lo = (uint32_t)fr * 64 + (uint32_t)(((hh + 2) ^ fsw) << 4);

    const int arow = (lane & 7) + 8 * ((lane >> 3) & 1);
    const int ac   = lane >> 4;
    const int asw  = (arow >> 1) & 3;
    const uint32_t aoff_hi = (uint32_t)arow * 64 + (uint32_t)((ac ^ asw) << 4);
    const uint32_t aoff_lo = (uint32_t)arow * 64 + (uint32_t)(((ac + 2) ^ asw) << 4);
    const int brow = (lane & 7) + 8 * (lane >> 4);
    const int bc   = (lane >> 3) & 1;
    const int bsw  = (brow >> 1) & 3;
    const uint32_t boff_hi = (uint32_t)brow * 64 + (uint32_t)((bc ^ bsw) << 4);
    const uint32_t boff_lo = (uint32_t)brow * 64 + (uint32_t)(((bc + 2) ^ bsw) << 4);

    auto load_A = [&](int c, float4& v0, float4& v1) {
        v0 = make_float4(0.f, 0.f, 0.f, 0.f); v1 = v0;
        if (valid) {
            const float* src = g_sum + (long long)fm * DD + c * 16 + hh * 8;
            v0 = ((const float4*)src)[0];
            v1 = ((const float4*)src)[1];
        }
    };
    auto store_A = [&](float4 v0, float4 v1, uint32_t stage) {
        uint4 hp, lp;
        split2(v0.x, v0.y, hp.x, lp.x);
        split2(v0.z, v0.w, hp.y, lp.y);
        split2(v1.x, v1.y, hp.z, lp.z);
        split2(v1.z, v1.w, hp.w, lp.w);
        *(uint4*)(smem + stage + a_dst_hi) = hp;
        *(uint4*)(smem + stage + a_dst_lo) = lp;
    };
    auto fill_B = [&](const unsigned short* Bsrc, int c, uint32_t dstb) {
        const char* base = (const char*)(Bsrc + (size_t)c * 128 * 32);
        #pragma unroll
        for (int i = 0; i < 2; i++) {
            int seg = tid + i * THREADS;
            int row = seg >> 2, cc = seg & 3;
            int sw = cc ^ ((row >> 1) & 3);
            CP16(sbase + dstb + row * 64 + sw * 16, base + row * 64 + cc * 16);
        }
    };

    float acc[2][8][4];
    #pragma unroll
    for (int mt = 0; mt < 2; mt++)
        #pragma unroll
        for (int nt = 0; nt < 8; nt++)
            #pragma unroll
            for (int e = 0; e < 4; e++) acc[mt][nt][e] = 0.f;

    auto compute = [&](uint32_t Aoff, uint32_t Boff) {
        uint32_t Ah[2][4], Al[2][4];
        #pragma unroll
        for (int mt = 0; mt < 2; mt++) {
            uint32_t ab = sbase + Aoff + (uint32_t)(warpM * 32 + mt * 16) * 64;
            LDM_X4(Ah[mt][0], Ah[mt][1], Ah[mt][2], Ah[mt][3], ab + aoff_hi);
            LDM_X4(Al[mt][0], Al[mt][1], Al[mt][2], Al[mt][3], ab + aoff_lo);
        }
        uint32_t Bh[2][4], Bl[2][4];
        {
            uint32_t bb = sbase + Boff + (uint32_t)(warpN * 64) * 64;
            LDM_X4(Bh[0][0], Bh[0][1], Bh[0][2], Bh[0][3], bb + boff_hi);
            LDM_X4(Bl[0][0], Bl[0][1], Bl[0][2], Bl[0][3], bb + boff_lo);
        }
        #pragma unroll
        for (int p = 0; p < 4; p++) {
            const int cur = p & 1, nxt = cur ^ 1;
            if (p < 3) {
                uint32_t bb = sbase + Boff + (uint32_t)(warpN * 64 + (p + 1) * 16) * 64;
                LDM_X4(Bh[nxt][0], Bh[nxt][1], Bh[nxt][2], Bh[nxt][3], bb + boff_hi);
                LDM_X4(Bl[nxt][0], Bl[nxt][1], Bl[nxt][2], Bl[nxt][3], bb + boff_lo);
            }
            #pragma unroll
            for (int q = 0; q < 2; q++) {
                const int nt = p * 2 + q;
                uint32_t bh0 = Bh[cur][q * 2], bh1 = Bh[cur][q * 2 + 1];
                uint32_t bl0 = Bl[cur][q * 2], bl1 = Bl[cur][q * 2 + 1];
                #pragma unroll
                for (int mt = 0; mt < 2; mt++) {
                    MMA_BF16(acc[mt][nt], Ah[mt], bh0, bh1);
                    MMA_BF16(acc[mt][nt], Ah[mt], bl0, bl1);
                    MMA_BF16(acc[mt][nt], Al[mt], bh0, bh1);
                }
            }
        }
    };

    // ================= GEMM1 (agg chunks = Bexp1 chunks 8..15) =============
    {
        float4 v0, v1;
        fill_B(Bexp1, 8, 0 + TILE); CP_COMMIT();
        load_A(0, v0, v1);
        store_A(v0, v1, 0);
        CP_WAIT0();
        __syncthreads();
    }
    #pragma unroll 1
    for (int c = 0; c < 8; c++) {
        const uint32_t st  = (uint32_t)(c & 1) * STAGE;
        const uint32_t nst = (uint32_t)((c + 1) & 1) * STAGE;
        float4 v0, v1;
        const bool more = (c + 1 < 8);
        if (more) {
            fill_B(Bexp1, 9 + c, nst + TILE); CP_COMMIT();
            load_A(c + 1, v0, v1);
        }
        compute(st, st + TILE);
        if (more) store_A(v0, v1, nst);
        CP_WAIT0();
        __syncthreads();
    }

    // ============ add partial D1 fragments ============
    #pragma unroll
    for (int mt = 0; mt < 2; mt++) {
        #pragma unroll
        for (int nt = 0; nt < 8; nt++) {
            int col = warpN * 64 + nt * 8 + (lane & 3) * 2;
            #pragma unroll
            for (int rr = 0; rr < 2; rr++) {
                int m = gm0 + warpM * 32 + mt * 16 + (lane >> 2) + rr * 8;
                if (m < M_NODES) {
                    float2 d = *(const float2*)(g_d1 + (long long)m * DD + col);
                    acc[mt][nt][rr * 2 + 0] += d.x;
                    acc[mt][nt][rr * 2 + 1] += d.y;
                }
            }
        }
    }

    // ============ epilogue 1: H = relu(D1+b1) -> SMEM ============
    fill_B(Bexp2, 0, 0 * TILE); CP_COMMIT();
    fill_B(Bexp2, 1, 1 * TILE); CP_COMMIT();

    #pragma unroll
    for (int mt = 0; mt < 2; mt++) {
        #pragma unroll
        for (int nt = 0; nt < 8; nt++) {
            int col = warpN * 64 + nt * 8 + (lane & 3) * 2;
            float bv0 = b1s[col], bv1 = b1s[col + 1];
            int cch = col >> 4, k0 = col & 15;
            int chi = k0 >> 3, kb = (k0 & 7) * 2;
            #pragma unroll
            for (int rr = 0; rr < 2; rr++) {
                int row = warpM * 32 + mt * 16 + (lane >> 2) + rr * 8;
                float h0 = fmaxf(acc[mt][nt][rr * 2 + 0] + bv0, 0.f);
                float h1 = fmaxf(acc[mt][nt][rr * 2 + 1] + bv1, 0.f);
                uint32_t hp, lp;
                split2(h0, h1, hp, lp);
                int sw = (row >> 1) & 3;
                char* dst = smem + HBASE + cch * TILE + row * 64;
                *(uint32_t*)(dst + ((chi ^ sw) << 4) + kb)       = hp;
                *(uint32_t*)(dst + (((chi + 2) ^ sw) << 4) + kb) = lp;
                acc[mt][nt][rr * 2 + 0] = 0.f;
                acc[mt][nt][rr * 2 + 1] = 0.f;
            }
        }
    }
    CP_WAIT1();
    __syncthreads();

    // ================= GEMM2 =================
    #pragma unroll 1
    for (int c = 0; c < NC2; c++) {
        const bool more = (c + 2 < NC2);
        if (more) { fill_B(Bexp2, c + 2, (uint32_t)((c + 2) & 3) * TILE); CP_COMMIT(); }
        compute(HBASE + c * TILE, (uint32_t)(c & 3) * TILE);
        if (more) CP_WAIT1(); else CP_WAIT0();
        __syncthreads();
    }

    // ============ epilogue 2 ============
    #pragma unroll
    for (int mt = 0; mt < 2; mt++) {
        #pragma unroll
        for (int nt = 0; nt < 8; nt++) {
            int col = warpN * 64 + nt * 8 + (lane & 3) * 2;
            float bv0 = b2s[col], bv1 = b2s[col + 1];
            #pragma unroll
            for (int rr = 0; rr < 2; rr++) {
                int m = gm0 + warpM * 32 + mt * 16 + (lane >> 2) + rr * 8;
                if (m < M_NODES) {
                    float2 o = make_float2(acc[mt][nt][rr * 2 + 0] + bv0,
                                           acc[mt][nt][rr * 2 + 1] + bv1);
                    *(float2*)(out + (long long)m * DD + col) = o;
                }
            }
        }
    }
}

// ---------------- host launcher --------------------------------------------
extern "C" void kernel_launch(void* const* d_in, const int* in_sizes, int n_in,
                              void* d_out, int out_size) {
    const float* x         = (const float*)d_in[0];
    const float* edge_attr = (const float*)d_in[1];
    const float* u         = (const float*)d_in[2];
    const float* W1        = (const float*)d_in[3];
    const float* b1        = (const float*)d_in[4];
    const float* W2        = (const float*)d_in[5];
    const float* b2        = (const float*)d_in[6];
    const void*  edge_index = d_in[7];
    const void*  batch      = d_in[8];
    float* out = (float*)d_out;

    static cudaStream_t s2 = nullptr;
    static cudaEvent_t evF = nullptr, evJ = nullptr;
    if (!s2) {
        cudaFuncSetAttribute(mlp_agg_mma,
                             cudaFuncAttributeMaxDynamicSharedMemorySize,
                             SMEM_TOTAL);
        cudaFuncSetAttribute(mlp_xu_mma,
                             cudaFuncAttributeMaxDynamicSharedMemorySize,
                             SMEM_P1);
        cudaStreamCreateWithFlags(&s2, cudaStreamNonBlocking);
        cudaEventCreateWithFlags(&evF, cudaEventDisableTiming);
        cudaEventCreateWithFlags(&evJ, cudaEventDisableTiming);
    }

    setup_kernel<<<NB_SCAN, 256>>>((const unsigned int*)edge_index, W1, W2);

    // fork: P1 (x,u partial GEMM) overlaps CSR build + gather
    cudaEventRecord(evF, 0);
    cudaStreamWaitEvent(s2, evF, 0);
    mlp_xu_mma<<<NTILES, THREADS, SMEM_P1, s2>>>(x, u, batch);
    cudaEventRecord(evJ, s2);

    hist_kernel<<<1184, 256>>>(edge_index);
    scan_kernel<<<NB_SCAN, 256>>>();
    fill_kernel<<<1184, 256>>>(edge_index);
    gather_kernel<<<(M_NODES * 32 + 255) / 256, 256>>>(edge_attr);

    // join: P2 needs g_d1 (P1) + g_sum (gather)
    cudaStreamWaitEvent(0, evJ, 0);
    mlp_agg_mma<<<NTILES, THREADS, SMEM_TOTAL>>>(b1, b2, out);
}

// round 13
// speedup vs baseline: 1.0405x; 1.0268x over previous
#include <cuda_runtime.h>
#include <cuda_bf16.h>
#include <cstdint>

#define M_NODES 100000
#define E_EDGES 1600000
#define DD      128
#define NGRAPH  16

#define NC1 24
#define NC2 8
#define TILE 8192
#define STAGE 16384

#define NB_SCAN ((M_NODES + 255) / 256)   // 391
#define NTILES  ((M_NODES + 127) / 128)   // 782

// ---------------- device scratch (static: allocation-free) ----------------
__device__ __align__(16) float g_sum[(size_t)M_NODES * DD];   // edge means
__device__ __align__(16) float g_d1[(size_t)M_NODES * DD];    // partial D1 (x,u)
__device__ int   g_cnt_i[M_NODES];
__device__ int   g_off[M_NODES];
__device__ int   g_cur[M_NODES];
__device__ int   g_perm[E_EDGES];
__device__ unsigned long long g_scan_desc[NB_SCAN];  // (status<<32)|value
__device__ int   g_ticket;
__device__ int   g_is64;
__device__ __align__(16) unsigned short Bexp1[NC1 * 128 * 32];
__device__ __align__(16) unsigned short Bexp2[NC2 * 128 * 32];

// ---------------- PTX helpers ----------------------------------------------
__device__ __forceinline__ uint32_t smem_u32(const void* p) {
    uint32_t a;
    asm("{ .reg .u64 t; cvta.to.shared.u64 t, %1; cvt.u32.u64 %0, t; }"
        : "=r"(a) : "l"(p));
    return a;
}
#define CP16(dst, src) \
    asm volatile("cp.async.ca.shared.global [%0], [%1], 16;" :: "r"(dst), "l"(src))
#define CP_COMMIT() asm volatile("cp.async.commit_group;" ::: "memory")
#define CP_WAIT1()  asm volatile("cp.async.wait_group 1;" ::: "memory")
#define CP_WAIT0()  asm volatile("cp.async.wait_group 0;" ::: "memory")
#define LDM_X4(r0, r1, r2, r3, a) \
    asm volatile("ldmatrix.sync.aligned.m8n8.x4.shared.b16 {%0,%1,%2,%3}, [%4];" \
                 : "=r"(r0), "=r"(r1), "=r"(r2), "=r"(r3) : "r"(a))
#define MMA_BF16(d, a, b0, b1) \
    asm volatile("mma.sync.aligned.m16n8k16.row.col.f32.bf16.bf16.f32 " \
                 "{%0,%1,%2,%3}, {%4,%5,%6,%7}, {%8,%9}, {%0,%1,%2,%3};" \
                 : "+f"((d)[0]), "+f"((d)[1]), "+f"((d)[2]), "+f"((d)[3]) \
                 : "r"((a)[0]), "r"((a)[1]), "r"((a)[2]), "r"((a)[3]), \
                   "r"(b0), "r"(b1))

__device__ __forceinline__ void split2(float v0, float v1,
                                       uint32_t& hp, uint32_t& lp) {
    uint32_t h2;
    asm("cvt.rn.bf16x2.f32 %0, %1, %2;" : "=r"(h2) : "f"(v1), "f"(v0));
    float h0 = __uint_as_float(h2 << 16);
    float h1 = __uint_as_float(h2 & 0xFFFF0000u);
    float l0 = v0 - h0, l1 = v1 - h1;
    asm("cvt.rn.bf16x2.f32 %0, %1, %2;" : "=r"(lp) : "f"(l1), "f"(l0));
    hp = h2;
}
__device__ __forceinline__ int edge_dest(const void* ei, int e, int is64) {
    return is64 ? (int)((const long long*)ei)[(long long)E_EDGES + e]
                : ((const int*)ei)[E_EDGES + e];
}

// ---------------- setup (small): dtype detect + zero counts + scan reset ----
__global__ void setup_small(const unsigned int* __restrict__ ei_words) {
    if (blockIdx.x == 0) {
        __shared__ unsigned int s;
        if (threadIdx.x == 0) s = 0u;
        __syncthreads();
        unsigned int v = 0u;
        for (int i = threadIdx.x; i < 8192; i += blockDim.x)
            v |= ei_words[2 * i + 1];
        atomicOr(&s, v);
        __syncthreads();
        if (threadIdx.x == 0) {
            g_is64 = (s == 0u) ? 1 : 0;
            g_ticket = 0;
        }
    }
    int i = blockIdx.x * blockDim.x + threadIdx.x;
    if (i < M_NODES) g_cnt_i[i] = 0;
    if (i < NB_SCAN) g_scan_desc[i] = 0ull;
}

// ---------------- weight prep (runs on s2, off the critical path) -----------
__global__ void prep_kernel(const float* __restrict__ W1,
                            const float* __restrict__ W2) {
    int i = blockIdx.x * blockDim.x + threadIdx.x;
    if (i < NC1 * 128 * 16) {
        int c = i >> 11, n = (i >> 4) & 127, k = i & 15;
        float w = W1[(c * 16 + k) * 128 + n];
        unsigned short h;
        asm("cvt.rn.bf16.f32 %0, %1;" : "=h"(h) : "f"(w));
        float l = w - __uint_as_float(((uint32_t)h) << 16);
        unsigned short lo;
        asm("cvt.rn.bf16.f32 %0, %1;" : "=h"(lo) : "f"(l));
        unsigned short* row = Bexp1 + ((size_t)c * 128 + n) * 32;
        row[k] = h; row[16 + k] = lo;
    }
    if (i < NC2 * 128 * 16) {
        int c = i >> 11, n = (i >> 4) & 127, k = i & 15;
        float w = W2[(c * 16 + k) * 128 + n];
        unsigned short h;
        asm("cvt.rn.bf16.f32 %0, %1;" : "=h"(h) : "f"(w));
        float l = w - __uint_as_float(((uint32_t)h) << 16);
        unsigned short lo;
        asm("cvt.rn.bf16.f32 %0, %1;" : "=h"(lo) : "f"(l));
        unsigned short* row = Bexp2 + ((size_t)c * 128 + n) * 32;
        row[k] = h; row[16 + k] = lo;
    }
}

// ---------------- CSR build --------------------------------------------------
__global__ void hist_kernel(const void* __restrict__ edge_index) {
    const int is64 = g_is64;
    const int stride = gridDim.x * blockDim.x;
    for (int e = blockIdx.x * blockDim.x + threadIdx.x; e < E_EDGES; e += stride)
        atomicAdd(&g_cnt_i[edge_dest(edge_index, e, is64)], 1);
}

// single-pass exclusive scan: ticket-ordered, WARP-PARALLEL decoupled lookback
__global__ void scan_kernel() {
    __shared__ int s[256];
    __shared__ int sbid;
    __shared__ int sprefix;
    const int lane = threadIdx.x & 31;
    if (threadIdx.x == 0) sbid = atomicAdd(&g_ticket, 1);
    __syncthreads();
    const int bid = sbid;
    const int i = bid * 256 + threadIdx.x;
    int v = (i < M_NODES) ? g_cnt_i[i] : 0;
    s[threadIdx.x] = v;
    __syncthreads();
    #pragma unroll
    for (int d = 1; d < 256; d <<= 1) {
        int w = (threadIdx.x >= d) ? s[threadIdx.x - d] : 0;
        __syncthreads();
        s[threadIdx.x] += w;
        __syncthreads();
    }
    const int total = s[255];
    if (threadIdx.x < 32) {
        if (bid == 0) {
            if (lane == 0) {
                atomicExch(&g_scan_desc[0],
                           (2ull << 32) | (unsigned long long)(unsigned int)total);
                sprefix = 0;
            }
        } else {
            if (lane == 0)
                atomicExch(&g_scan_desc[bid],
                           (1ull << 32) | (unsigned long long)(unsigned int)total);
            int excl = 0;
            int j = bid - 1;
            while (true) {
                const int idx = j - lane;            // lane 0 = newest block
                unsigned long long d = 0;
                int status = 2;                      // idx<0 => identity prefix
                if (idx >= 0) {
                    do {
                        d = atomicAdd(&g_scan_desc[idx], 0ull);
                        status = (int)(d >> 32);
                    } while (status == 0);
                }
                const unsigned pm = __ballot_sync(0xffffffffu, status == 2);
                const int lim = pm ? (__ffs(pm) - 1) : 32;  // nearest prefix-done
                int val = (lane <= lim) ? (int)(unsigned int)d : 0;
                #pragma unroll
                for (int o = 16; o > 0; o >>= 1)
                    val += __shfl_down_sync(0xffffffffu, val, o);
                val = __shfl_sync(0xffffffffu, val, 0);
                excl += val;
                if (pm) break;
                j -= 32;
            }
            if (lane == 0) {
                atomicExch(&g_scan_desc[bid],
                           (2ull << 32) |
                           (unsigned long long)(unsigned int)(excl + total));
                sprefix = excl;
            }
        }
    }
    __syncthreads();
    if (i < M_NODES) {
        int off = sprefix + s[threadIdx.x] - v;   // exclusive
        g_off[i] = off;
        g_cur[i] = off;
    }
}

__global__ void fill_kernel(const void* __restrict__ edge_index) {
    const int is64 = g_is64;
    const int stride = gridDim.x * blockDim.x;
    for (int e = blockIdx.x * blockDim.x + threadIdx.x; e < E_EDGES; e += stride) {
        int d = edge_dest(edge_index, e, is64);
        int pos = atomicAdd(&g_cur[d], 1);
        g_perm[pos] = e;
    }
}

// ---------------- gather: warp per node, writes MEAN -------------------------
__global__ void gather_kernel(const float* __restrict__ edge_attr) {
    const int w    = (blockIdx.x * blockDim.x + threadIdx.x) >> 5;
    const int lane = threadIdx.x & 31;
    if (w >= M_NODES) return;
    const int off = g_off[w];
    const int cnt = g_cnt_i[w];
    float4 acc = make_float4(0.f, 0.f, 0.f, 0.f);
    int j = 0;
    for (; j + 8 <= cnt; j += 8) {
        float4 v[8];
        #pragma unroll
        for (int q = 0; q < 8; q++) {
            int e = g_perm[off + j + q];
            v[q] = __ldcs((const float4*)(edge_attr + (long long)e * DD + lane * 4));
        }
        #pragma unroll
        for (int q = 0; q < 8; q++) {
            acc.x += v[q].x; acc.y += v[q].y; acc.z += v[q].z; acc.w += v[q].w;
        }
    }
    for (; j < cnt; j++) {
        int e = g_perm[off + j];
        float4 v = __ldcs((const float4*)(edge_attr + (long long)e * DD + lane * 4));
        acc.x += v.x; acc.y += v.y; acc.z += v.z; acc.w += v.w;
    }
    float s = 1.0f / fmaxf((float)cnt, 1.0f);
    acc.x *= s; acc.y *= s; acc.z *= s; acc.w *= s;
    *(float4*)(g_sum + (long long)w * DD + lane * 4) = acc;
}

// ---------------- P1: D1_partial = x*W1x + u*W1u (fragments -> g_d1) ---------
#define THREADS 256
#define SMEM_P1 (2 * STAGE + 64)

__global__ __launch_bounds__(THREADS, 2)
void mlp_xu_mma(const float* __restrict__ x,
                const float* __restrict__ u,
                const void*  __restrict__ batch_ptr) {
    extern __shared__ char smem[];
    const uint32_t sbase = smem_u32(smem);
    const int tid   = threadIdx.x;
    const int wid   = tid >> 5;
    const int lane  = tid & 31;
    const int warpM = wid >> 1;
    const int warpN = wid & 1;
    const int gm0   = blockIdx.x * 128;

    const int fr = tid >> 1;
    const int hh = tid & 1;
    const int fm = gm0 + fr;
    const bool valid = fm < M_NODES;
    long long ub = 0;
    if (valid)
        ub = g_is64 ? ((const long long*)batch_ptr)[fm]
                    : (long long)((const int*)batch_ptr)[fm];
    const int fsw = (fr >> 1) & 3;
    const uint32_t a_dst_hi = (uint32_t)fr * 64 + (uint32_t)((hh ^ fsw) << 4);
    const uint32_t a_dst_lo = (uint32_t)fr * 64 + (uint32_t)(((hh + 2) ^ fsw) << 4);

    const int arow = (lane & 7) + 8 * ((lane >> 3) & 1);
    const int ac   = lane >> 4;
    const int asw  = (arow >> 1) & 3;
    const uint32_t aoff_hi = (uint32_t)arow * 64 + (uint32_t)((ac ^ asw) << 4);
    const uint32_t aoff_lo = (uint32_t)arow * 64 + (uint32_t)(((ac + 2) ^ asw) << 4);
    const int brow = (lane & 7) + 8 * (lane >> 4);
    const int bc   = (lane >> 3) & 1;
    const int bsw  = (brow >> 1) & 3;
    const uint32_t boff_hi = (uint32_t)brow * 64 + (uint32_t)((bc ^ bsw) << 4);
    const uint32_t boff_lo = (uint32_t)brow * 64 + (uint32_t)(((bc + 2) ^ bsw) << 4);

    auto load_A = [&](int c, float4& v0, float4& v1) {
        v0 = make_float4(0.f, 0.f, 0.f, 0.f); v1 = v0;
        if (valid) {
            const float* src = (c < 8)
                ? x + (long long)fm * DD + c * 16 + hh * 8
                : u + ub * DD + (c - 8) * 16 + hh * 8;
            v0 = ((const float4*)src)[0];
            v1 = ((const float4*)src)[1];
        }
    };
    auto store_A = [&](float4 v0, float4 v1, uint32_t stage) {
        uint4 hp, lp;
        split2(v0.x, v0.y, hp.x, lp.x);
        split2(v0.z, v0.w, hp.y, lp.y);
        split2(v1.x, v1.y, hp.z, lp.z);
        split2(v1.z, v1.w, hp.w, lp.w);
        *(uint4*)(smem + stage + a_dst_hi) = hp;
        *(uint4*)(smem + stage + a_dst_lo) = lp;
    };
    auto fill_B = [&](int c, uint32_t dstb) {
        const int orig = (c < 8) ? c : (c + 8);   // x chunks 0..7, u chunks 16..23
        const char* base = (const char*)(Bexp1 + (size_t)orig * 128 * 32);
        #pragma unroll
        for (int i = 0; i < 2; i++) {
            int seg = tid + i * THREADS;
            int row = seg >> 2, cc = seg & 3;
            int sw = cc ^ ((row >> 1) & 3);
            CP16(sbase + dstb + row * 64 + sw * 16, base + row * 64 + cc * 16);
        }
    };

    float acc[2][8][4];
    #pragma unroll
    for (int mt = 0; mt < 2; mt++)
        #pragma unroll
        for (int nt = 0; nt < 8; nt++)
            #pragma unroll
            for (int e = 0; e < 4; e++) acc[mt][nt][e] = 0.f;

    auto compute = [&](uint32_t Aoff, uint32_t Boff) {
        uint32_t Ah[2][4], Al[2][4];
        #pragma unroll
        for (int mt = 0; mt < 2; mt++) {
            uint32_t ab = sbase + Aoff + (uint32_t)(warpM * 32 + mt * 16) * 64;
            LDM_X4(Ah[mt][0], Ah[mt][1], Ah[mt][2], Ah[mt][3], ab + aoff_hi);
            LDM_X4(Al[mt][0], Al[mt][1], Al[mt][2], Al[mt][3], ab + aoff_lo);
        }
        uint32_t Bh[2][4], Bl[2][4];
        {
            uint32_t bb = sbase + Boff + (uint32_t)(warpN * 64) * 64;
            LDM_X4(Bh[0][0], Bh[0][1], Bh[0][2], Bh[0][3], bb + boff_hi);
            LDM_X4(Bl[0][0], Bl[0][1], Bl[0][2], Bl[0][3], bb + boff_lo);
        }
        #pragma unroll
        for (int p = 0; p < 4; p++) {
            const int cur = p & 1, nxt = cur ^ 1;
            if (p < 3) {
                uint32_t bb = sbase + Boff + (uint32_t)(warpN * 64 + (p + 1) * 16) * 64;
                LDM_X4(Bh[nxt][0], Bh[nxt][1], Bh[nxt][2], Bh[nxt][3], bb + boff_hi);
                LDM_X4(Bl[nxt][0], Bl[nxt][1], Bl[nxt][2], Bl[nxt][3], bb + boff_lo);
            }
            #pragma unroll
            for (int q = 0; q < 2; q++) {
                const int nt = p * 2 + q;
                uint32_t bh0 = Bh[cur][q * 2], bh1 = Bh[cur][q * 2 + 1];
                uint32_t bl0 = Bl[cur][q * 2], bl1 = Bl[cur][q * 2 + 1];
                #pragma unroll
                for (int mt = 0; mt < 2; mt++) {
                    MMA_BF16(acc[mt][nt], Ah[mt], bh0, bh1);
                    MMA_BF16(acc[mt][nt], Ah[mt], bl0, bl1);
                    MMA_BF16(acc[mt][nt], Al[mt], bh0, bh1);
                }
            }
        }
    };

    {
        float4 v0, v1;
        fill_B(0, 0 + TILE); CP_COMMIT();
        load_A(0, v0, v1);
        store_A(v0, v1, 0);
        CP_WAIT0();
        __syncthreads();
    }
    #pragma unroll 1
    for (int c = 0; c < 16; c++) {
        const uint32_t st  = (uint32_t)(c & 1) * STAGE;
        const uint32_t nst = (uint32_t)((c + 1) & 1) * STAGE;
        float4 v0, v1;
        const bool more = (c + 1 < 16);
        if (more) {
            fill_B(c + 1, nst + TILE); CP_COMMIT();
            load_A(c + 1, v0, v1);
        }
        compute(st, st + TILE);
        if (more) store_A(v0, v1, nst);
        CP_WAIT0();
        __syncthreads();
    }

    // store raw fragments to g_d1 (no bias/relu)
    #pragma unroll
    for (int mt = 0; mt < 2; mt++) {
        #pragma unroll
        for (int nt = 0; nt < 8; nt++) {
            int col = warpN * 64 + nt * 8 + (lane & 3) * 2;
            #pragma unroll
            for (int rr = 0; rr < 2; rr++) {
                int m = gm0 + warpM * 32 + mt * 16 + (lane >> 2) + rr * 8;
                if (m < M_NODES) {
                    *(float2*)(g_d1 + (long long)m * DD + col) =
                        make_float2(acc[mt][nt][rr * 2 + 0], acc[mt][nt][rr * 2 + 1]);
                }
            }
        }
    }
}

// ---------------- P2: agg GEMM + d1 add + relu + GEMM2 -----------------------
#define HBASE   32768
#define CTRL    98304
#define SMEM_TOTAL (CTRL + 1024)

__global__ __launch_bounds__(THREADS, 2)
void mlp_agg_mma(const float* __restrict__ b1,
                 const float* __restrict__ b2,
                 float* __restrict__ out) {
    extern __shared__ char smem[];
    const uint32_t sbase = smem_u32(smem);
    const int tid   = threadIdx.x;
    const int wid   = tid >> 5;
    const int lane  = tid & 31;
    const int warpM = wid >> 1;
    const int warpN = wid & 1;
    const int gm0   = blockIdx.x * 128;

    float* b1s = (float*)(smem + CTRL);
    float* b2s = (float*)(smem + CTRL + 512);
    if (tid < 128) b1s[tid] = b1[tid];
    else b2s[tid - 128] = b2[tid - 128];

    const int fr = tid >> 1;
    const int hh = tid & 1;
    const int fm = gm0 + fr;
    const bool valid = fm < M_NODES;
    const int fsw = (fr >> 1) & 3;
    const uint32_t a_dst_hi = (uint32_t)fr * 64 + (uint32_t)((hh ^ fsw) << 4);
    const uint32_t a_dst_lo = (uint32_t)fr * 64 + (uint32_t)(((hh + 2) ^ fsw) << 4);

    const int arow = (lane & 7) + 8 * ((lane >> 3) & 1);
    const int ac   = lane >> 4;
    const int asw  = (arow >> 1) & 3;
    const uint32_t aoff_hi = (uint32_t)arow * 64 + (uint32_t)((ac ^ asw) << 4);
    const uint32_t aoff_lo = (uint32_t)arow * 64 + (uint32_t)(((ac + 2) ^ asw) << 4);
    const int brow = (lane & 7) + 8 * (lane >> 4);
    const int bc   = (lane >> 3) & 1;
    const int bsw  = (brow >> 1) & 3;
    const uint32_t boff_hi = (uint32_t)brow * 64 + (uint32_t)((bc ^ bsw) << 4);
    const uint32_t boff_lo = (uint32_t)brow * 64 + (uint32_t)(((bc + 2) ^ bsw) << 4);

    auto load_A = [&](int c, float4& v0, float4& v1) {
        v0 = make_float4(0.f, 0.f, 0.f, 0.f); v1 = v0;
        if (valid) {
            const float* src = g_sum + (long long)fm * DD + c * 16 + hh * 8;
            v0 = ((const float4*)src)[0];
            v1 = ((const float4*)src)[1];
        }
    };
    auto store_A = [&](float4 v0, float4 v1, uint32_t stage) {
        uint4 hp, lp;
        split2(v0.x, v0.y, hp.x, lp.x);
        split2(v0.z, v0.w, hp.y, lp.y);
        split2(v1.x, v1.y, hp.z, lp.z);
        split2(v1.z, v1.w, hp.w, lp.w);
        *(uint4*)(smem + stage + a_dst_hi) = hp;
        *(uint4*)(smem + stage + a_dst_lo) = lp;
    };
    auto fill_B = [&](const unsigned short* Bsrc, int c, uint32_t dstb) {
        const char* base = (const char*)(Bsrc + (size_t)c * 128 * 32);
        #pragma unroll
        for (int i = 0; i < 2; i++) {
            int seg = tid + i * THREADS;
            int row = seg >> 2, cc = seg & 3;
            int sw = cc ^ ((row >> 1) & 3);
            CP16(sbase + dstb + row * 64 + sw * 16, base + row * 64 + cc * 16);
        }
    };

    float acc[2][8][4];
    #pragma unroll
    for (int mt = 0; mt < 2; mt++)
        #pragma unroll
        for (int nt = 0; nt < 8; nt++)
            #pragma unroll
            for (int e = 0; e < 4; e++) acc[mt][nt][e] = 0.f;

    auto compute = [&](uint32_t Aoff, uint32_t Boff) {
        uint32_t Ah[2][4], Al[2][4];
        #pragma unroll
        for (int mt = 0; mt < 2; mt++) {
            uint32_t ab = sbase + Aoff + (uint32_t)(warpM * 32 + mt * 16) * 64;
            LDM_X4(Ah[mt][0], Ah[mt][1], Ah[mt][2], Ah[mt][3], ab + aoff_hi);
            LDM_X4(Al[mt][0], Al[mt][1], Al[mt][2], Al[mt][3], ab + aoff_lo);
        }
        uint32_t Bh[2][4], Bl[2][4];
        {
            uint32_t bb = sbase + Boff + (uint32_t)(warpN * 64) * 64;
            LDM_X4(Bh[0][0], Bh[0][1], Bh[0][2], Bh[0][3], bb + boff_hi);
            LDM_X4(Bl[0][0], Bl[0][1], Bl[0][2], Bl[0][3], bb + boff_lo);
        }
        #pragma unroll
        for (int p = 0; p < 4; p++) {
            const int cur = p & 1, nxt = cur ^ 1;
            if (p < 3) {
                uint32_t bb = sbase + Boff + (uint32_t)(warpN * 64 + (p + 1) * 16) * 64;
                LDM_X4(Bh[nxt][0], Bh[nxt][1], Bh[nxt][2], Bh[nxt][3], bb + boff_hi);
                LDM_X4(Bl[nxt][0], Bl[nxt][1], Bl[nxt][2], Bl[nxt][3], bb + boff_lo);
            }
            #pragma unroll
            for (int q = 0; q < 2; q++) {
                const int nt = p * 2 + q;
                uint32_t bh0 = Bh[cur][q * 2], bh1 = Bh[cur][q * 2 + 1];
                uint32_t bl0 = Bl[cur][q * 2], bl1 = Bl[cur][q * 2 + 1];
                #pragma unroll
                for (int mt = 0; mt < 2; mt++) {
                    MMA_BF16(acc[mt][nt], Ah[mt], bh0, bh1);
                    MMA_BF16(acc[mt][nt], Ah[mt], bl0, bl1);
                    MMA_BF16(acc[mt][nt], Al[mt], bh0, bh1);
                }
            }
        }
    };

    // ================= GEMM1 (agg chunks = Bexp1 chunks 8..15) =============
    {
        float4 v0, v1;
        fill_B(Bexp1, 8, 0 + TILE); CP_COMMIT();
        load_A(0, v0, v1);
        store_A(v0, v1, 0);
        CP_WAIT0();
        __syncthreads();
    }
    #pragma unroll 1
    for (int c = 0; c < 8; c++) {
        const uint32_t st  = (uint32_t)(c & 1) * STAGE;
        const uint32_t nst = (uint32_t)((c + 1) & 1) * STAGE;
        float4 v0, v1;
        const bool more = (c + 1 < 8);
        if (more) {
            fill_B(Bexp1, 9 + c, nst + TILE); CP_COMMIT();
            load_A(c + 1, v0, v1);
        }
        compute(st, st + TILE);
        if (more) store_A(v0, v1, nst);
        CP_WAIT0();
        __syncthreads();
    }

    // ============ add partial D1 fragments ============
    #pragma unroll
    for (int mt = 0; mt < 2; mt++) {
        #pragma unroll
        for (int nt = 0; nt < 8; nt++) {
            int col = warpN * 64 + nt * 8 + (lane & 3) * 2;
            #pragma unroll
            for (int rr = 0; rr < 2; rr++) {
                int m = gm0 + warpM * 32 + mt * 16 + (lane >> 2) + rr * 8;
                if (m < M_NODES) {
                    float2 d = *(const float2*)(g_d1 + (long long)m * DD + col);
                    acc[mt][nt][rr * 2 + 0] += d.x;
                    acc[mt][nt][rr * 2 + 1] += d.y;
                }
            }
        }
    }

    // ============ epilogue 1: H = relu(D1+b1) -> SMEM ============
    fill_B(Bexp2, 0, 0 * TILE); CP_COMMIT();
    fill_B(Bexp2, 1, 1 * TILE); CP_COMMIT();

    #pragma unroll
    for (int mt = 0; mt < 2; mt++) {
        #pragma unroll
        for (int nt = 0; nt < 8; nt++) {
            int col = warpN * 64 + nt * 8 + (lane & 3) * 2;
            float bv0 = b1s[col], bv1 = b1s[col + 1];
            int cch = col >> 4, k0 = col & 15;
            int chi = k0 >> 3, kb = (k0 & 7) * 2;
            #pragma unroll
            for (int rr = 0; rr < 2; rr++) {
                int row = warpM * 32 + mt * 16 + (lane >> 2) + rr * 8;
                float h0 = fmaxf(acc[mt][nt][rr * 2 + 0] + bv0, 0.f);
                float h1 = fmaxf(acc[mt][nt][rr * 2 + 1] + bv1, 0.f);
                uint32_t hp, lp;
                split2(h0, h1, hp, lp);
                int sw = (row >> 1) & 3;
                char* dst = smem + HBASE + cch * TILE + row * 64;
                *(uint32_t*)(dst + ((chi ^ sw) << 4) + kb)       = hp;
                *(uint32_t*)(dst + (((chi + 2) ^ sw) << 4) + kb) = lp;
                acc[mt][nt][rr * 2 + 0] = 0.f;
                acc[mt][nt][rr * 2 + 1] = 0.f;
            }
        }
    }
    CP_WAIT1();
    __syncthreads();

    // ================= GEMM2 =================
    #pragma unroll 1
    for (int c = 0; c < NC2; c++) {
        const bool more = (c + 2 < NC2);
        if (more) { fill_B(Bexp2, c + 2, (uint32_t)((c + 2) & 3) * TILE); CP_COMMIT(); }
        compute(HBASE + c * TILE, (uint32_t)(c & 3) * TILE);
        if (more) CP_WAIT1(); else CP_WAIT0();
        __syncthreads();
    }

    // ============ epilogue 2 ============
    #pragma unroll
    for (int mt = 0; mt < 2; mt++) {
        #pragma unroll
        for (int nt = 0; nt < 8; nt++) {
            int col = warpN * 64 + nt * 8 + (lane & 3) * 2;
            float bv0 = b2s[col], bv1 = b2s[col + 1];
            #pragma unroll
            for (int rr = 0; rr < 2; rr++) {
                int m = gm0 + warpM * 32 + mt * 16 + (lane >> 2) + rr * 8;
                if (m < M_NODES) {
                    float2 o = make_float2(acc[mt][nt][rr * 2 + 0] + bv0,
                                           acc[mt][nt][rr * 2 + 1] + bv1);
                    *(float2*)(out + (long long)m * DD + col) = o;
                }
            }
        }
    }
}

// ---------------- host launcher --------------------------------------------
extern "C" void kernel_launch(void* const* d_in, const int* in_sizes, int n_in,
                              void* d_out, int out_size) {
    const float* x         = (const float*)d_in[0];
    const float* edge_attr = (const float*)d_in[1];
    const float* u         = (const float*)d_in[2];
    const float* W1        = (const float*)d_in[3];
    const float* b1        = (const float*)d_in[4];
    const float* W2        = (const float*)d_in[5];
    const float* b2        = (const float*)d_in[6];
    const void*  edge_index = d_in[7];
    const void*  batch      = d_in[8];
    float* out = (float*)d_out;

    static cudaStream_t s2 = nullptr;
    static cudaEvent_t evF = nullptr, evJ = nullptr;
    if (!s2) {
        cudaFuncSetAttribute(mlp_agg_mma,
                             cudaFuncAttributeMaxDynamicSharedMemorySize,
                             SMEM_TOTAL);
        cudaFuncSetAttribute(mlp_xu_mma,
                             cudaFuncAttributeMaxDynamicSharedMemorySize,
                             SMEM_P1);
        cudaStreamCreateWithFlags(&s2, cudaStreamNonBlocking);
        cudaEventCreateWithFlags(&evF, cudaEventDisableTiming);
        cudaEventCreateWithFlags(&evJ, cudaEventDisableTiming);
    }

    setup_small<<<NB_SCAN, 256>>>((const unsigned int*)edge_index);

    // fork: weight prep + P1 (x,u partial GEMM) overlap CSR build + gather
    cudaEventRecord(evF, 0);
    cudaStreamWaitEvent(s2, evF, 0);
    prep_kernel<<<192, 256, 0, s2>>>(W1, W2);
    mlp_xu_mma<<<NTILES, THREADS, SMEM_P1, s2>>>(x, u, batch);
    cudaEventRecord(evJ, s2);

    hist_kernel<<<1184, 256>>>(edge_index);
    scan_kernel<<<NB_SCAN, 256>>>();
    fill_kernel<<<1184, 256>>>(edge_index);
    gather_kernel<<<(M_NODES * 32 + 255) / 256, 256>>>(edge_attr);

    // join: P2 needs g_d1 (P1) + g_sum (gather)
    cudaStreamWaitEvent(0, evJ, 0);
    mlp_agg_mma<<<NTILES, THREADS, SMEM_TOTAL>>>(b1, b2, out);
}